// round 17
// baseline (speedup 1.0000x reference)
#include <cuda_runtime.h>
#include <cuda_fp16.h>

typedef unsigned int u32;

// CostVolume via banded fp16 GEMM (mma.sync m16n8k16, fp32 accumulate),
// two-phase channel pipeline: phase-B globals prefetched into registers
// while phase-A computes (breaks the fill/compute convoy; DRAM-bound now).
// Block = (bh, 128-w tile), 256 threads / 8 warps.
// Warp wid: G[16,80] = L[16 rows] . R[80 rows]^T (R row r <-> src=w0-64+r),
// out[w,d] = G[w_l, w_l+63-d]/64, masked where src = w-1-d < 0.

namespace {
constexpr int Wd = 512, Cd = 64, Dd = 64, WT = 128;
constexpr int PH        = 40;               // pitch (halves) per 32-ch phase
constexpr int L_HALVES  = 128 * PH;         // 5120
constexpr int BUF_HALVES = (128 + 192) * PH;  // 12800 (25.6 KB)
constexpr int SMEM_BYTES = 2 * BUF_HALVES * 2; // 51,200
constexpr int STG_P     = 68;               // staging pitch (f32 words)
}

__device__ __forceinline__ void mma_f16(float* d, const u32* a, u32 b0, u32 b1) {
    asm("mma.sync.aligned.m16n8k16.row.col.f32.f16.f16.f32 "
        "{%0,%1,%2,%3}, {%4,%5,%6,%7}, {%8,%9}, {%0,%1,%2,%3};"
        : "+f"(d[0]), "+f"(d[1]), "+f"(d[2]), "+f"(d[3])
        : "r"(a[0]), "r"(a[1]), "r"(a[2]), "r"(a[3]), "r"(b0), "r"(b1));
}
__device__ __forceinline__ u32 pack_h2(float lo, float hi) {
    const __half2 h = __floats2half2_rn(lo, hi);
    return *(const u32*)&h;
}

__global__ __launch_bounds__(256, 2)
void cost_volume_mma_kernel(const float* __restrict__ left,
                            const float* __restrict__ right,
                            float* __restrict__ out) {
    extern __shared__ __half smh[];

    const int tid  = threadIdx.x;
    const int wid  = tid >> 5;        // 0..7
    const int lane = tid & 31;
    const int q    = lane >> 2;       // 0..7
    const int c    = lane & 3;        // 0..3
    const int w0   = blockIdx.x * WT;
    const int bh   = blockIdx.y;

    const float* lrow = left  + (size_t)bh * Wd * Cd;
    const float* rrow = right + (size_t)bh * Wd * Cd;

    // fill indexing: per phase, L = 4 items, R = 6 items per thread
    const int frow = tid >> 3;        // base row (stride 32)
    const int fc4  = tid & 7;         // 16B column chunk within 32 channels

    // ---- phase A: load + convert + store (channels 0..31) ----
    {
        float4 lv[4], rv[6];
#pragma unroll
        for (int i = 0; i < 4; i++)
            lv[i] = *(const float4*)(lrow + (size_t)(w0 + frow + 32 * i) * Cd + 4 * fc4);
#pragma unroll
        for (int i = 0; i < 6; i++) {
            const int s = max(w0 - 64 + frow + 32 * i, 0);
            rv[i] = *(const float4*)(rrow + (size_t)s * Cd + 4 * fc4);
        }
#pragma unroll
        for (int i = 0; i < 4; i++) {
            const uint2 t = make_uint2(pack_h2(lv[i].x, lv[i].y), pack_h2(lv[i].z, lv[i].w));
            *(uint2*)&smh[(frow + 32 * i) * PH + 4 * fc4] = t;
        }
#pragma unroll
        for (int i = 0; i < 6; i++) {
            const uint2 t = make_uint2(pack_h2(rv[i].x, rv[i].y), pack_h2(rv[i].z, rv[i].w));
            *(uint2*)&smh[L_HALVES + (frow + 32 * i) * PH + 4 * fc4] = t;
        }
    }

    // ---- issue phase-B LDGs (channels 32..63), consumed after compute A ----
    float4 lvb[4], rvb[6];
#pragma unroll
    for (int i = 0; i < 4; i++)
        lvb[i] = *(const float4*)(lrow + (size_t)(w0 + frow + 32 * i) * Cd + 32 + 4 * fc4);
#pragma unroll
    for (int i = 0; i < 6; i++) {
        const int s = max(w0 - 64 + frow + 32 * i, 0);
        rvb[i] = *(const float4*)(rrow + (size_t)s * Cd + 32 + 4 * fc4);
    }
    __syncthreads();

    float acc[10][4];
#pragma unroll
    for (int nt = 0; nt < 10; nt++)
#pragma unroll
        for (int r = 0; r < 4; r++) acc[nt][r] = 0.0f;

    const int la_off = (16 * wid + q) * PH;
    const int rb_off = L_HALVES + (16 * wid + q) * PH;

    // ---- compute phase A (k = 0..31) ----
    {
        const __half* la = smh + la_off;
        const __half* rb = smh + rb_off;
#pragma unroll
        for (int ki = 0; ki < 2; ki++) {
            const int kb = 16 * ki + 4 * c;
            const uint2 alo = *(const uint2*)(la + kb);
            const uint2 ahi = *(const uint2*)(la + 8 * PH + kb);
            const u32 a[4] = {alo.x, ahi.x, alo.y, ahi.y};
#pragma unroll
            for (int nt = 0; nt < 10; nt++) {
                const uint2 bb = *(const uint2*)(rb + (8 * nt) * PH + kb);
                mma_f16(acc[nt], a, bb.x, bb.y);
            }
        }
    }

    // ---- convert + store phase B ----
#pragma unroll
    for (int i = 0; i < 4; i++) {
        const uint2 t = make_uint2(pack_h2(lvb[i].x, lvb[i].y), pack_h2(lvb[i].z, lvb[i].w));
        *(uint2*)&smh[BUF_HALVES + (frow + 32 * i) * PH + 4 * fc4] = t;
    }
#pragma unroll
    for (int i = 0; i < 6; i++) {
        const uint2 t = make_uint2(pack_h2(rvb[i].x, rvb[i].y), pack_h2(rvb[i].z, rvb[i].w));
        *(uint2*)&smh[BUF_HALVES + L_HALVES + (frow + 32 * i) * PH + 4 * fc4] = t;
    }
    __syncthreads();

    // ---- compute phase B (k = 32..63) ----
    {
        const __half* la = smh + BUF_HALVES + la_off;
        const __half* rb = smh + BUF_HALVES + rb_off;
#pragma unroll
        for (int ki = 0; ki < 2; ki++) {
            const int kb = 16 * ki + 4 * c;
            const uint2 alo = *(const uint2*)(la + kb);
            const uint2 ahi = *(const uint2*)(la + 8 * PH + kb);
            const u32 a[4] = {alo.x, ahi.x, alo.y, ahi.y};
#pragma unroll
            for (int nt = 0; nt < 10; nt++) {
                const uint2 bb = *(const uint2*)(rb + (8 * nt) * PH + kb);
                mma_f16(acc[nt], a, bb.x, bb.y);
            }
        }
    }

    // ---- epilogue: diagonal extraction into smem staging ----
    __syncthreads();
    float* stage = (float*)smh;                   // [128][STG_P] f32
    const float scale = 1.0f / 64.0f;
#pragma unroll
    for (int nt = 0; nt < 10; nt++)
#pragma unroll
        for (int r = 0; r < 4; r++) {
            const int d = 63 + q + 8 * (r >> 1) - 8 * nt - 2 * c - (r & 1);
            if (d >= 0 && d < 64) {
                const int w_l = 16 * wid + q + 8 * (r >> 1);
                const int s_l = w_l + 63 - d;
                const float val = (w0 + s_l >= 64) ? acc[nt][r] * scale : 0.0f;
                stage[w_l * STG_P + d] = val;
            }
        }
    __syncthreads();

    // ---- coalesced copy staging -> gmem ----
#pragma unroll
    for (int i = 0; i < 8; i++) {
        const int idx = tid + 256 * i;           // 0..2047
        const int row = idx >> 4, c4 = idx & 15;
        const float4 v = *(const float4*)(stage + row * STG_P + 4 * c4);
        *(float4*)(out + ((size_t)bh * Wd + w0 + row) * Dd + 4 * c4) = v;
    }
}

extern "C" void kernel_launch(void* const* d_in, const int* in_sizes, int n_in,
                              void* d_out, int out_size) {
    const float* left  = (const float*)d_in[0];
    const float* right = (const float*)d_in[1];
    float* outp = (float*)d_out;

    const int BH = in_sizes[0] / (Wd * Cd);

    cudaFuncSetAttribute(cost_volume_mma_kernel,
                         cudaFuncAttributeMaxDynamicSharedMemorySize, SMEM_BYTES);
    dim3 grid(Wd / WT, BH, 1);
    cost_volume_mma_kernel<<<grid, 256, SMEM_BYTES>>>(left, right, outp);
}